// round 2
// baseline (speedup 1.0000x reference)
#include <cuda_runtime.h>
#include <math.h>

#define B_   256
#define C_   512
#define L_   2048
#define HID  32
#define FL   8

// Scratch (no allocations allowed)
__device__ float g_stat[B_ * C_];   // 512 KB
__device__ float g_loss[B_];        // per-sample ortho loss

// ---------------------------------------------------------------------------
// Kernel 1: stat[b,c] = max over L of x[b,c,:]   (HBM-bound, 1 GiB read)
// One warp per row of 2048 floats. float4 loads, 16 per lane, coalesced.
// ---------------------------------------------------------------------------
__global__ void __launch_bounds__(256) dywan_max_kernel(
    const float* __restrict__ x, float* __restrict__ stat)
{
    const int warp = threadIdx.x >> 5;
    const int lane = threadIdx.x & 31;
    const int row  = blockIdx.x * 8 + warp;          // 16384 blocks * 8 warps = 131072 rows

    const float4* p = reinterpret_cast<const float4*>(x + (size_t)row * L_);

    float m = -INFINITY;
#pragma unroll
    for (int i = 0; i < 16; ++i) {
        float4 v = p[lane + 32 * i];
        m = fmaxf(m, fmaxf(fmaxf(v.x, v.y), fmaxf(v.z, v.w)));
    }
#pragma unroll
    for (int o = 16; o > 0; o >>= 1)
        m = fmaxf(m, __shfl_xor_sync(0xFFFFFFFFu, m, o));

    if (lane == 0) stat[row] = m;
}

// ---------------------------------------------------------------------------
// Kernel 2: per-sample MLP + filters + per-sample ortho loss.
// 256 blocks (one per batch sample) x 32 threads. Weights stay hot in L2.
// ---------------------------------------------------------------------------
__global__ void __launch_bounds__(32) dywan_mlp_kernel(
    const float* __restrict__ stat,
    const float* __restrict__ W1, const float* __restrict__ b1,
    const float* __restrict__ W2, const float* __restrict__ b2,
    const float* __restrict__ W3, const float* __restrict__ b3,
    float* __restrict__ out, float* __restrict__ loss)
{
    __shared__ float s[C_];
    __shared__ float h1[HID];
    __shared__ float h2[HID];
    __shared__ float f[2 * FL];

    const int b = blockIdx.x;
    const int t = threadIdx.x;   // 0..31

    // Load stat row into shared (32 lanes x 4 float4 = 512 floats)
    const float4* sp = reinterpret_cast<const float4*>(stat + (size_t)b * C_);
    float4* ss = reinterpret_cast<float4*>(s);
#pragma unroll
    for (int i = 0; i < 4; ++i) ss[t + 32 * i] = sp[t + 32 * i];
    __syncwarp();

    // Layer 1: h1 = relu(W1 @ s + b1), each lane computes one of 32 outputs
    {
        float a = b1[t];
        const float* w = W1 + (size_t)t * C_;
#pragma unroll 8
        for (int c = 0; c < C_; ++c) a = fmaf(w[c], s[c], a);
        h1[t] = fmaxf(a, 0.0f);
    }
    __syncwarp();

    // Layer 2: h2 = relu(W2 @ h1 + b2)
    {
        float a = b2[t];
        const float* w = W2 + t * HID;
#pragma unroll
        for (int k = 0; k < HID; ++k) a = fmaf(w[k], h1[k], a);
        h2[t] = fmaxf(a, 0.0f);
    }
    __syncwarp();

    // Layer 3: filters = W3 @ h2 + b3  (16 outputs)
    if (t < 2 * FL) {
        float a = b3[t];
        const float* w = W3 + t * HID;
#pragma unroll
        for (int k = 0; k < HID; ++k) a = fmaf(w[k], h2[k], a);
        f[t] = a;
        if (t < FL) out[(size_t)b * FL + t] = a;                         // lo
        else        out[(size_t)B_ * FL + (size_t)b * FL + (t - FL)] = a; // hi
    }
    __syncwarp();

    // Per-sample ortho loss (trivial 8-element work, lane 0)
    if (t == 0) {
        float lo[FL], hi[FL];
        float nl = 0.0f, nh = 0.0f;
#pragma unroll
        for (int i = 0; i < FL; ++i) {
            lo[i] = f[i]; hi[i] = f[FL + i];
            nl += lo[i] * lo[i];
            nh += hi[i] * hi[i];
        }
        const float il = 1.0f / sqrtf(nl);
        const float ih = 1.0f / sqrtf(nh);
        float Ln[FL], Hn[FL];
#pragma unroll
        for (int i = 0; i < FL; ++i) { Ln[i] = lo[i] * il; Hn[i] = hi[i] * ih; }

        float acc = 0.0f;
        // shifts s = 1, 3, 5, 7 ;  roll(Ln, s)[i] = Ln[(i - s) mod 8]
#pragma unroll
        for (int sft = 1; sft < FL; sft += 2) {
            float d = 0.0f;
#pragma unroll
            for (int i = 0; i < FL; ++i) d += Ln[i] * Ln[(i - sft + FL) & (FL - 1)];
            acc += fabsf(d);
        }
        float dlh = 0.0f, dll = 0.0f, dhh = 0.0f;
#pragma unroll
        for (int i = 0; i < FL; ++i) {
            dlh += Ln[i] * Hn[i];
            dll += Ln[i] * Ln[i];
            dhh += Hn[i] * Hn[i];
        }
        acc += fabsf(dlh) + fabsf(dll - 1.0f) + fabsf(dhh - 1.0f);
        loss[b] = acc;
    }
}

// ---------------------------------------------------------------------------
// Kernel 3: deterministic tree-reduction of the 256 per-sample losses.
// ---------------------------------------------------------------------------
__global__ void __launch_bounds__(256) dywan_reduce_kernel(
    const float* __restrict__ loss, float* __restrict__ out)
{
    __shared__ float sm[B_];
    const int t = threadIdx.x;
    sm[t] = loss[t];
    __syncthreads();
#pragma unroll
    for (int o = 128; o > 0; o >>= 1) {
        if (t < o) sm[t] += sm[t + o];
        __syncthreads();
    }
    if (t == 0) out[2 * B_ * FL] = sm[0] * (1.0f / (float)B_);
}

// ---------------------------------------------------------------------------
extern "C" void kernel_launch(void* const* d_in, const int* in_sizes, int n_in,
                              void* d_out, int out_size)
{
    const float* x  = (const float*)d_in[0];
    const float* W1 = (const float*)d_in[1];
    const float* b1 = (const float*)d_in[2];
    const float* W2 = (const float*)d_in[3];
    const float* b2 = (const float*)d_in[4];
    const float* W3 = (const float*)d_in[5];
    const float* b3 = (const float*)d_in[6];
    float* out = (float*)d_out;

    float* stat;  cudaGetSymbolAddress((void**)&stat, g_stat);
    float* loss;  cudaGetSymbolAddress((void**)&loss, g_loss);

    dywan_max_kernel<<<(B_ * C_) / 8, 256>>>(x, stat);
    dywan_mlp_kernel<<<B_, 32>>>(stat, W1, b1, W2, b2, W3, b3, out, loss);
    dywan_reduce_kernel<<<1, 256>>>(loss, out);
}